// round 13
// baseline (speedup 1.0000x reference)
#include <cuda_runtime.h>
#include <cuda_bf16.h>
#include <cstdint>

#define BATCH 1024
#define MF 1024
#define NF 512
#define LAMBDv 0.2f
#define TOL2 1e-8f
#define MAX_ITERS 100

// iteration GEMM tiling: CTA tile 64(M) x 64(N), K chunks of 64
#define KC 64
#define NCHUNK (MF / KC)            // 16
#define SROW 72                     // smem row stride in bf16 (144B, ldmatrix conflict-free)
#define SROW2 (SROW * 2)
#define TILEB (64 * SROW2)          // 9216 per tile (A or B, hi or lo)
#define STAGEB (4 * TILEB)          // 36864
#define DYN_SMEM (2 * STAGEB)       // 73728
#define NCTA 256                    // grid 16 x 16

// ---------------- device scratch ----------------
__device__ __align__(256) float g_Adb[BATCH * MF];
__device__ __align__(256) float g_u[BATCH * MF];
__device__ __align__(256) float g_v[BATCH * MF];
__device__ __align__(256) __nv_bfloat16 g_behi[2][BATCH * MF];
__device__ __align__(256) __nv_bfloat16 g_belo[2][BATCH * MF];
__device__ __align__(256) __nv_bfloat16 g_mThi[MF * MF];
__device__ __align__(256) __nv_bfloat16 g_mTlo[MF * MF];
__device__ float g_dx2p[BATCH * 16];
__device__ float g_x2p[BATCH * 16];
__device__ int g_solved[BATCH];
__device__ int g_idx[BATCH];
__device__ int g_nact;
__device__ int g_done;

// ---------------- helpers ----------------
__device__ __forceinline__ uint32_t smem_u32(const void* p) {
    uint32_t a;
    asm("{ .reg .u64 t; cvta.to.shared.u64 t, %1; cvt.u32.u64 %0, t; }" : "=r"(a) : "l"(p));
    return a;
}
__device__ __forceinline__ void ldm_x4(unsigned* r, uint32_t addr) {
    asm volatile("ldmatrix.sync.aligned.m8n8.x4.shared.b16 {%0,%1,%2,%3}, [%4];"
        : "=r"(r[0]), "=r"(r[1]), "=r"(r[2]), "=r"(r[3]) : "r"(addr));
}
__device__ __forceinline__ void cpa16(uint32_t dst, const void* src) {
    asm volatile("cp.async.cg.shared.global [%0], [%1], 16;" :: "r"(dst), "l"(src));
}
#define CP_COMMIT() asm volatile("cp.async.commit_group;" ::: "memory")
#define CP_WAIT(n)  asm volatile("cp.async.wait_group %0;" :: "n"(n) : "memory")

__device__ __forceinline__ void mma16816(float* c, const unsigned* a, const unsigned* b) {
    asm volatile(
        "mma.sync.aligned.m16n8k16.row.col.f32.bf16.bf16.f32 "
        "{%0,%1,%2,%3}, {%4,%5,%6,%7}, {%8,%9}, {%0,%1,%2,%3};"
        : "+f"(c[0]), "+f"(c[1]), "+f"(c[2]), "+f"(c[3])
        : "r"(a[0]), "r"(a[1]), "r"(a[2]), "r"(a[3]), "r"(b[0]), "r"(b[1]));
}
__device__ __forceinline__ void bsplit(float x, __nv_bfloat16& h, __nv_bfloat16& l) {
    h = __float2bfloat16(x);
    l = __float2bfloat16(x - __bfloat162float(h));
}

// ---------------- init ----------------
__global__ void init_kernel() {
    int i = blockIdx.x * blockDim.x + threadIdx.x;  // BATCH*MF/4
    float4 z = make_float4(0.f, 0.f, 0.f, 0.f);
    ((float4*)g_u)[i] = z;
    ((float4*)g_v)[i] = z;
    if (i < BATCH) { g_solved[i] = 0; g_idx[i] = i; }
    if (i == 0) { g_nact = BATCH; g_done = 0; }
}

// ---------------- Minv -> transposed bf16 hi/lo split ----------------
__global__ void prep_minv(const float* __restrict__ Minv) {
    __shared__ float t[32][33];
    int bx = blockIdx.x * 32, by = blockIdx.y * 32;
    for (int i = threadIdx.y; i < 32; i += 8)
        t[i][threadIdx.x] = Minv[(size_t)(by + i) * MF + bx + threadIdx.x];
    __syncthreads();
    for (int i = threadIdx.y; i < 32; i += 8) {
        int n = bx + i, k = by + threadIdx.x;
        __nv_bfloat16 h, l;
        bsplit(t[threadIdx.x][i], h, l);  // Minv[k][n] -> MinvT[n][k]
        g_mThi[(size_t)n * MF + k] = h;
        g_mTlo[(size_t)n * MF + k] = l;
    }
}

// ---------------- A_dot_b = x @ W^T ; seeds beff[0] split (u=v=0) ----------------
__global__ void gemm_nt_kernel(const float* __restrict__ X, const float* __restrict__ W) {
    __shared__ float As[16][64];
    __shared__ float Bs[16][64];
    int tid = threadIdx.x;
    int row0 = blockIdx.y * 64, col0 = blockIdx.x * 64;
    int lr = tid >> 2, kq = tid & 3;
    int tm = tid >> 4, tn = tid & 15;
    float acc[4][4] = {};
    for (int k0 = 0; k0 < NF; k0 += 16) {
        float4 a4 = *(const float4*)(X + (size_t)(row0 + lr) * NF + k0 + kq * 4);
        float4 b4 = *(const float4*)(W + (size_t)(col0 + lr) * NF + k0 + kq * 4);
        __syncthreads();
        As[kq * 4 + 0][lr] = a4.x; As[kq * 4 + 1][lr] = a4.y;
        As[kq * 4 + 2][lr] = a4.z; As[kq * 4 + 3][lr] = a4.w;
        Bs[kq * 4 + 0][lr] = b4.x; Bs[kq * 4 + 1][lr] = b4.y;
        Bs[kq * 4 + 2][lr] = b4.z; Bs[kq * 4 + 3][lr] = b4.w;
        __syncthreads();
#pragma unroll
        for (int kk = 0; kk < 16; kk++) {
            float4 av = *(const float4*)&As[kk][tm * 4];
            float4 bv = *(const float4*)&Bs[kk][tn * 4];
            float a[4] = {av.x, av.y, av.z, av.w};
            float b[4] = {bv.x, bv.y, bv.z, bv.w};
#pragma unroll
            for (int i = 0; i < 4; i++)
#pragma unroll
                for (int j = 0; j < 4; j++) acc[i][j] += a[i] * b[j];
        }
    }
#pragma unroll
    for (int i = 0; i < 4; i++) {
        size_t base = (size_t)(row0 + tm * 4 + i) * MF + col0 + tn * 4;
        *(float4*)(g_Adb + base) = make_float4(acc[i][0], acc[i][1], acc[i][2], acc[i][3]);
#pragma unroll
        for (int j = 0; j < 4; j++) {
            __nv_bfloat16 h, l;
            bsplit(acc[i][j], h, l);
            g_behi[0][base + j] = h;
            g_belo[0][base + j] = l;
        }
    }
}

// ---------------- per-iteration: compacted-row mma GEMM + ADMM epilogue + converge + compact ----------------
// Tile 64(act-M) x 64(N); 4 warps as 2(M) x 2(N), warp tile 32x32.
// A rows gathered through g_idx (all gathered rows are unsolved by construction).
__global__ void __launch_bounds__(128, 3) admm_iter(int p) {
    extern __shared__ __align__(16) char sraw[];
    __shared__ float red_dx[64][2];
    __shared__ float red_x2[64][2];
    __shared__ int s_last;
    __shared__ int pref[128];

    const int tid = threadIdx.x;
    const int lane = tid & 31;
    const int w = tid >> 5;
    const int warp_m = w & 1;
    const int warp_n = w >> 1;
    const int nact = g_nact;
    const int row0 = blockIdx.y * 64;
    const int col0 = blockIdx.x * 64;
    const int pn = p ^ 1;
    const bool work = (row0 < nact);

    if (work) {
        const uint32_t sb = smem_u32(sraw);
        const int cs = tid & 7;
        const int a0 = tid >> 3;  // base local row (0..15)

        // gather indices for this thread's 4 A-rows (local rows a0+16j)
        int aidx[4];
#pragma unroll
        for (int j = 0; j < 4; j++) {
            int lr = a0 + 16 * j;
            aidx[j] = (row0 + lr < nact) ? g_idx[row0 + lr] : 0;
        }

        // issue chunk 0
        {
            const __nv_bfloat16* ah = g_behi[p];
            const __nv_bfloat16* al = g_belo[p];
#pragma unroll
            for (int j = 0; j < 4; j++) {
                int lr = a0 + 16 * j;
                uint32_t doff = (uint32_t)lr * SROW2 + cs * 16;
                const size_t aoff = (size_t)aidx[j] * MF + cs * 8;
                const size_t boff = (size_t)(col0 + lr) * MF + cs * 8;
                cpa16(sb + doff, ah + aoff);
                cpa16(sb + TILEB + doff, al + aoff);
                cpa16(sb + 2 * TILEB + doff, g_mThi + boff);
                cpa16(sb + 3 * TILEB + doff, g_mTlo + boff);
            }
        }
        CP_COMMIT();

        float c[2][4][4] = {};
        const uint32_t a_off = (uint32_t)(warp_m * 32 + (lane & 15)) * SROW2 + (lane >> 4) * 16;
        const uint32_t b_off = (uint32_t)(warp_n * 32 + (lane & 7) + ((lane >> 4) & 1) * 8) * SROW2
                             + ((lane >> 3) & 1) * 16;

        for (int t = 0; t < NCHUNK; t++) {
            int s = t & 1;
            if (t + 1 < NCHUNK) {
                int kb = (t + 1) * KC;
                uint32_t stb = sb + ((t + 1) & 1) * STAGEB;
                const __nv_bfloat16* ah = g_behi[p];
                const __nv_bfloat16* al = g_belo[p];
#pragma unroll
                for (int j = 0; j < 4; j++) {
                    int lr = a0 + 16 * j;
                    uint32_t doff = (uint32_t)lr * SROW2 + cs * 16;
                    const size_t aoff = (size_t)aidx[j] * MF + kb + cs * 8;
                    const size_t boff = (size_t)(col0 + lr) * MF + kb + cs * 8;
                    cpa16(stb + doff, ah + aoff);
                    cpa16(stb + TILEB + doff, al + aoff);
                    cpa16(stb + 2 * TILEB + doff, g_mThi + boff);
                    cpa16(stb + 3 * TILEB + doff, g_mTlo + boff);
                }
                CP_COMMIT();
                CP_WAIT(1);
            } else {
                CP_WAIT(0);
            }
            __syncthreads();

            const uint32_t Ah = sb + s * STAGEB;
            const uint32_t Al = Ah + TILEB;
            const uint32_t Bh = Ah + 2 * TILEB;
            const uint32_t Bl = Ah + 3 * TILEB;
#pragma unroll
            for (int kk = 0; kk < 4; kk++) {
                const uint32_t kb32 = kk * 32;
                unsigned ah[2][4], al[2][4], bh[2][4], bl[2][4];
#pragma unroll
                for (int fm = 0; fm < 2; fm++) {
                    uint32_t ao = a_off + (uint32_t)(fm * 16) * SROW2 + kb32;
                    ldm_x4(ah[fm], Ah + ao);
                    ldm_x4(al[fm], Al + ao);
                }
#pragma unroll
                for (int pr = 0; pr < 2; pr++) {
                    uint32_t bo = b_off + (uint32_t)(pr * 16) * SROW2 + kb32;
                    ldm_x4(bh[pr], Bh + bo);
                    ldm_x4(bl[pr], Bl + bo);
                }
#pragma unroll
                for (int fm = 0; fm < 2; fm++)
#pragma unroll
                    for (int fn = 0; fn < 4; fn++) {
                        const unsigned* ph = &bh[fn >> 1][(fn & 1) * 2];
                        const unsigned* pl = &bl[fn >> 1][(fn & 1) * 2];
                        mma16816(c[fm][fn], ah[fm], ph);
                        mma16816(c[fm][fn], ah[fm], pl);
                        mma16816(c[fm][fn], al[fm], ph);
                    }
            }
            __syncthreads();
        }

        // ---- fused ADMM epilogue (all gathered rows are unsolved) ----
        float pdx[2][2] = {}, px2[2][2] = {};
#pragma unroll
        for (int fm = 0; fm < 2; fm++) {
#pragma unroll
            for (int rs = 0; rs < 2; rs++) {
                int lrow = warp_m * 32 + fm * 16 + rs * 8 + (lane >> 2);
                int valid = (row0 + lrow < nact);
                int r = valid ? g_idx[row0 + lrow] : 0;
                float ldx = 0.f, lx2 = 0.f;
                if (valid) {
#pragma unroll
                    for (int fn = 0; fn < 4; fn++) {
                        int cc = col0 + warp_n * 32 + fn * 8 + (lane & 3) * 2;
                        size_t base = (size_t)r * MF + cc;
                        float2 u2 = *(const float2*)(g_u + base);
                        float2 v2 = *(const float2*)(g_v + base);
                        float2 a2 = *(const float2*)(g_Adb + base);
                        float uu[2] = {u2.x, u2.y}, vv[2] = {v2.x, v2.y}, aa[2] = {a2.x, a2.y};
                        float un[2], vn[2];
#pragma unroll
                        for (int jj = 0; jj < 2; jj++) {
                            float xk = c[fm][fn][rs * 2 + jj];
                            float tt = xk + uu[jj];
                            float av = fabsf(tt) - LAMBDv;
                            float sft = (av > 0.f) ? copysignf(av, tt) : 0.f;
                            un[jj] = tt - sft;
                            vn[jj] = sft;
                            float d = sft - vv[jj];
                            ldx += d * d;
                            lx2 += sft * sft;
                        }
                        *(float2*)(g_u + base) = make_float2(un[0], un[1]);
                        *(float2*)(g_v + base) = make_float2(vn[0], vn[1]);
                        __nv_bfloat16 h0, l0, h1, l1;
                        bsplit(aa[0] + vn[0] - un[0], h0, l0);
                        bsplit(aa[1] + vn[1] - un[1], h1, l1);
                        *(__nv_bfloat162*)(g_behi[pn] + base) = __halves2bfloat162(h0, h1);
                        *(__nv_bfloat162*)(g_belo[pn] + base) = __halves2bfloat162(l0, l1);
                    }
                }
                pdx[fm][rs] = ldx;
                px2[fm][rs] = lx2;
            }
        }
#pragma unroll
        for (int fm = 0; fm < 2; fm++) {
#pragma unroll
            for (int rs = 0; rs < 2; rs++) {
                float a = pdx[fm][rs], b = px2[fm][rs];
                a += __shfl_xor_sync(0xffffffffu, a, 1);
                a += __shfl_xor_sync(0xffffffffu, a, 2);
                b += __shfl_xor_sync(0xffffffffu, b, 1);
                b += __shfl_xor_sync(0xffffffffu, b, 2);
                if ((lane & 3) == 0) {
                    int rl = warp_m * 32 + fm * 16 + rs * 8 + (lane >> 2);
                    red_dx[rl][warp_n] = a;
                    red_x2[rl][warp_n] = b;
                }
            }
        }
        __syncthreads();
        if (tid < 64 && row0 + tid < nact) {
            int r = g_idx[row0 + tid];
            g_dx2p[r * 16 + blockIdx.x] = red_dx[tid][0] + red_dx[tid][1];
            g_x2p[r * 16 + blockIdx.x] = red_x2[tid][0] + red_x2[tid][1];
        }
    }

    // ---- arrival; last CTA updates solved flags and recompacts ----
    __threadfence();
    __syncthreads();
    if (tid == 0) s_last = (atomicAdd(&g_done, 1) == NCTA - 1);
    __syncthreads();
    if (s_last) {
        int loc[8];
        int cnt = 0;
#pragma unroll
        for (int k = 0; k < 8; k++) {
            int r = tid * 8 + k;
            int slv = g_solved[r];
            if (!slv) {
                float sdx = 0.f, sx2 = 0.f;
#pragma unroll
                for (int j = 0; j < 16; j++) { sdx += g_dx2p[r * 16 + j]; sx2 += g_x2p[r * 16 + j]; }
                if (sdx < TOL2 * sx2) { g_solved[r] = 1; slv = 1; }
            }
            loc[k] = !slv;
            cnt += loc[k];
        }
        pref[tid] = cnt;
        __syncthreads();
        for (int off = 1; off < 128; off <<= 1) {
            int val = (tid >= off) ? pref[tid - off] : 0;
            __syncthreads();
            pref[tid] += val;
            __syncthreads();
        }
        int pos = pref[tid] - cnt;
#pragma unroll
        for (int k = 0; k < 8; k++) {
            if (loc[k]) g_idx[pos++] = tid * 8 + k;
        }
        if (tid == 127) { g_nact = pref[127]; g_done = 0; }
    }
}

// ---------------- enc = solved ? v : 0 ----------------
__global__ void finalize_enc(float* __restrict__ enc) {
    int i = blockIdx.x * blockDim.x + threadIdx.x;  // BATCH*MF/4
    int row = i / (MF / 4);
    float4 vv = ((const float4*)g_v)[i];
    float4 z = make_float4(0.f, 0.f, 0.f, 0.f);
    ((float4*)enc)[i] = g_solved[row] ? vv : z;
}

// ---------------- decoded = encoded @ W ----------------
__global__ void gemm_decode_kernel(const float* __restrict__ W, const float* __restrict__ enc,
                                   float* __restrict__ dec) {
    __shared__ float As[16][64];
    __shared__ float Bs[16][64];
    int tid = threadIdx.x;
    int row0 = blockIdx.y * 64, col0 = blockIdx.x * 64;
    int lr = tid >> 2, kq = tid & 3;
    int kr = tid >> 4, nq = tid & 15;
    int tm = tid >> 4, tn = tid & 15;
    float acc[4][4] = {};
    for (int k0 = 0; k0 < MF; k0 += 16) {
        float4 a4 = *(const float4*)(enc + (size_t)(row0 + lr) * MF + k0 + kq * 4);
        float4 b4 = *(const float4*)(W + (size_t)(k0 + kr) * NF + col0 + nq * 4);
        __syncthreads();
        As[kq * 4 + 0][lr] = a4.x; As[kq * 4 + 1][lr] = a4.y;
        As[kq * 4 + 2][lr] = a4.z; As[kq * 4 + 3][lr] = a4.w;
        *(float4*)&Bs[kr][nq * 4] = b4;
        __syncthreads();
#pragma unroll
        for (int kk = 0; kk < 16; kk++) {
            float4 av = *(const float4*)&As[kk][tm * 4];
            float4 bv = *(const float4*)&Bs[kk][tn * 4];
            float a[4] = {av.x, av.y, av.z, av.w};
            float b[4] = {bv.x, bv.y, bv.z, bv.w};
#pragma unroll
            for (int i = 0; i < 4; i++)
#pragma unroll
                for (int j = 0; j < 4; j++) acc[i][j] += a[i] * b[j];
        }
    }
#pragma unroll
    for (int i = 0; i < 4; i++) {
        float4 o = make_float4(acc[i][0], acc[i][1], acc[i][2], acc[i][3]);
        *(float4*)(dec + (size_t)(row0 + tm * 4 + i) * NF + col0 + tn * 4) = o;
    }
}

// ---------------- launch ----------------
extern "C" void kernel_launch(void* const* d_in, const int* in_sizes, int n_in,
                              void* d_out, int out_size) {
    const float* x = (const float*)d_in[0];      // (1024, 512)
    const float* w = (const float*)d_in[1];      // (1024, 512)
    const float* Minv = (const float*)d_in[2];   // (1024, 1024)
    float* out = (float*)d_out;
    float* enc = out;
    float* dec = out + BATCH * MF;

    static int attr_done = 0;
    if (!attr_done) {
        cudaFuncSetAttribute(admm_iter, cudaFuncAttributeMaxDynamicSharedMemorySize, DYN_SMEM);
        attr_done = 1;
    }

    init_kernel<<<BATCH * MF / 4 / 256, 256>>>();
    prep_minv<<<dim3(32, 32), dim3(32, 8)>>>(Minv);
    gemm_nt_kernel<<<dim3(MF / 64, BATCH / 64), 256>>>(x, w);

    for (int it = 0; it < MAX_ITERS; it++) {
        admm_iter<<<dim3(16, 16), 128, DYN_SMEM>>>(it & 1);
    }

    finalize_enc<<<BATCH * MF / 4 / 256, 256>>>(enc);
    gemm_decode_kernel<<<dim3(NF / 64, BATCH / 64), 256>>>(w, enc, dec);
}

// round 16
// speedup vs baseline: 1.4121x; 1.4121x over previous
#include <cuda_runtime.h>
#include <cuda_bf16.h>
#include <cstdint>

#define BATCH 1024
#define MF 1024
#define NF 512
#define LAMBDv 0.2f
#define TOL2 1e-8f
#define MAX_ITERS 100

// iteration GEMM tiling: CTA tile 128(M) x 64(N), K chunks of 64
#define KC 64
#define NCHUNK (MF / KC)            // 16
#define SROW 72                     // smem row stride in bf16 (144B, ldmatrix conflict-free)
#define SROW2 (SROW * 2)
#define TILEB_A (128 * SROW2)       // 18432
#define TILEB_B (64 * SROW2)        // 9216
#define STAGEB (2 * TILEB_A + 2 * TILEB_B)  // 55296
#define DYN_SMEM (2 * STAGEB)       // 110592

// ---------------- device scratch ----------------
__device__ __align__(256) float g_Adb[BATCH * MF];
__device__ __align__(256) float g_u[BATCH * MF];
__device__ __align__(256) float g_v[BATCH * MF];
__device__ __align__(256) __nv_bfloat16 g_behi[2][BATCH * MF];
__device__ __align__(256) __nv_bfloat16 g_belo[2][BATCH * MF];
__device__ __align__(256) __nv_bfloat16 g_mThi[MF * MF];
__device__ __align__(256) __nv_bfloat16 g_mTlo[MF * MF];
__device__ float g_dx2p[BATCH * 16];
__device__ float g_x2p[BATCH * 16];
__device__ int g_solved[BATCH];
__device__ int g_idx[BATCH];
__device__ int g_nact;

// ---------------- helpers ----------------
__device__ __forceinline__ uint32_t smem_u32(const void* p) {
    uint32_t a;
    asm("{ .reg .u64 t; cvta.to.shared.u64 t, %1; cvt.u32.u64 %0, t; }" : "=r"(a) : "l"(p));
    return a;
}
__device__ __forceinline__ void ldm_x4(unsigned* r, uint32_t addr) {
    asm volatile("ldmatrix.sync.aligned.m8n8.x4.shared.b16 {%0,%1,%2,%3}, [%4];"
        : "=r"(r[0]), "=r"(r[1]), "=r"(r[2]), "=r"(r[3]) : "r"(addr));
}
__device__ __forceinline__ void cpa16(uint32_t dst, const void* src) {
    asm volatile("cp.async.cg.shared.global [%0], [%1], 16;" :: "r"(dst), "l"(src));
}
#define CP_COMMIT() asm volatile("cp.async.commit_group;" ::: "memory")
#define CP_WAIT(n)  asm volatile("cp.async.wait_group %0;" :: "n"(n) : "memory")

__device__ __forceinline__ void mma16816(float* c, const unsigned* a, const unsigned* b) {
    asm volatile(
        "mma.sync.aligned.m16n8k16.row.col.f32.bf16.bf16.f32 "
        "{%0,%1,%2,%3}, {%4,%5,%6,%7}, {%8,%9}, {%0,%1,%2,%3};"
        : "+f"(c[0]), "+f"(c[1]), "+f"(c[2]), "+f"(c[3])
        : "r"(a[0]), "r"(a[1]), "r"(a[2]), "r"(a[3]), "r"(b[0]), "r"(b[1]));
}
__device__ __forceinline__ void bsplit(float x, __nv_bfloat16& h, __nv_bfloat16& l) {
    h = __float2bfloat16(x);
    l = __float2bfloat16(x - __bfloat162float(h));
}

// ---------------- init ----------------
__global__ void init_kernel() {
    int i = blockIdx.x * blockDim.x + threadIdx.x;  // BATCH*MF/4
    float4 z = make_float4(0.f, 0.f, 0.f, 0.f);
    ((float4*)g_u)[i] = z;
    ((float4*)g_v)[i] = z;
    if (i < BATCH) { g_solved[i] = 0; g_idx[i] = i; }
    if (i == 0) g_nact = BATCH;
}

// ---------------- Minv -> transposed bf16 hi/lo split ----------------
__global__ void prep_minv(const float* __restrict__ Minv) {
    __shared__ float t[32][33];
    int bx = blockIdx.x * 32, by = blockIdx.y * 32;
    for (int i = threadIdx.y; i < 32; i += 8)
        t[i][threadIdx.x] = Minv[(size_t)(by + i) * MF + bx + threadIdx.x];
    __syncthreads();
    for (int i = threadIdx.y; i < 32; i += 8) {
        int n = bx + i, k = by + threadIdx.x;
        __nv_bfloat16 h, l;
        bsplit(t[threadIdx.x][i], h, l);  // Minv[k][n] -> MinvT[n][k]
        g_mThi[(size_t)n * MF + k] = h;
        g_mTlo[(size_t)n * MF + k] = l;
    }
}

// ---------------- A_dot_b = x @ W^T ; seeds beff[0] split (u=v=0) ----------------
__global__ void gemm_nt_kernel(const float* __restrict__ X, const float* __restrict__ W) {
    __shared__ float As[16][64];
    __shared__ float Bs[16][64];
    int tid = threadIdx.x;
    int row0 = blockIdx.y * 64, col0 = blockIdx.x * 64;
    int lr = tid >> 2, kq = tid & 3;
    int tm = tid >> 4, tn = tid & 15;
    float acc[4][4] = {};
    for (int k0 = 0; k0 < NF; k0 += 16) {
        float4 a4 = *(const float4*)(X + (size_t)(row0 + lr) * NF + k0 + kq * 4);
        float4 b4 = *(const float4*)(W + (size_t)(col0 + lr) * NF + k0 + kq * 4);
        __syncthreads();
        As[kq * 4 + 0][lr] = a4.x; As[kq * 4 + 1][lr] = a4.y;
        As[kq * 4 + 2][lr] = a4.z; As[kq * 4 + 3][lr] = a4.w;
        Bs[kq * 4 + 0][lr] = b4.x; Bs[kq * 4 + 1][lr] = b4.y;
        Bs[kq * 4 + 2][lr] = b4.z; Bs[kq * 4 + 3][lr] = b4.w;
        __syncthreads();
#pragma unroll
        for (int kk = 0; kk < 16; kk++) {
            float4 av = *(const float4*)&As[kk][tm * 4];
            float4 bv = *(const float4*)&Bs[kk][tn * 4];
            float a[4] = {av.x, av.y, av.z, av.w};
            float b[4] = {bv.x, bv.y, bv.z, bv.w};
#pragma unroll
            for (int i = 0; i < 4; i++)
#pragma unroll
                for (int j = 0; j < 4; j++) acc[i][j] += a[i] * b[j];
        }
    }
#pragma unroll
    for (int i = 0; i < 4; i++) {
        size_t base = (size_t)(row0 + tm * 4 + i) * MF + col0 + tn * 4;
        *(float4*)(g_Adb + base) = make_float4(acc[i][0], acc[i][1], acc[i][2], acc[i][3]);
#pragma unroll
        for (int j = 0; j < 4; j++) {
            __nv_bfloat16 h, l;
            bsplit(acc[i][j], h, l);
            g_behi[0][base + j] = h;
            g_belo[0][base + j] = l;
        }
    }
}

// ---------------- per-iteration mma.sync GEMM + fused ADMM epilogue (compacted rows) ----------------
// Tile 128(act-M) x 64(N); 8 warps as 4(M) x 2(N), warp tile 32x32.
// A rows gathered through g_idx; all gathered rows are unsolved by construction.
__global__ void __launch_bounds__(256, 1) admm_iter(int p) {
    const int nact = g_nact;
    const int row0 = blockIdx.y * 128;
    if (row0 >= nact) return;
    extern __shared__ __align__(16) char sraw[];
    __shared__ float red_dx[128][2];
    __shared__ float red_x2[128][2];

    const int tid = threadIdx.x;
    const int lane = tid & 31;
    const int w = tid >> 5;
    const int warp_m = w & 3;   // 4 warps x 32 rows
    const int warp_n = w >> 2;  // 2 warps x 32 cols
    const int col0 = blockIdx.x * 64;
    const int pn = p ^ 1;

    const uint32_t sb = smem_u32(sraw);
    const int cs = tid & 7;
    const int ar = tid >> 3;               // base A row slot (0..31), rows ar+32j
    const int rB = tid >> 3;               // B rows: rB, rB+32 (j=0..1)

    // gather global row indices for this thread's 4 A-row slots
    int aidx[4];
#pragma unroll
    for (int j = 0; j < 4; j++) {
        int lr = ar + 32 * j;
        aidx[j] = (row0 + lr < nact) ? g_idx[row0 + lr] : 0;
    }

    // issue chunk 0
    {
        const __nv_bfloat16* ah = g_behi[p];
        const __nv_bfloat16* al = g_belo[p];
#pragma unroll
        for (int j = 0; j < 4; j++) {
            int lr = ar + 32 * j;
            uint32_t doff = (uint32_t)lr * SROW2 + cs * 16;
            const size_t aoff = (size_t)aidx[j] * MF + cs * 8;
            cpa16(sb + doff, ah + aoff);
            cpa16(sb + TILEB_A + doff, al + aoff);
        }
#pragma unroll
        for (int j = 0; j < 2; j++) {
            int lr = rB + 32 * j;
            uint32_t doff = (uint32_t)lr * SROW2 + cs * 16;
            const size_t boff = (size_t)(col0 + lr) * MF + cs * 8;
            cpa16(sb + 2 * TILEB_A + doff, g_mThi + boff);
            cpa16(sb + 2 * TILEB_A + TILEB_B + doff, g_mTlo + boff);
        }
    }
    CP_COMMIT();

    float c[2][4][4] = {};
    const uint32_t a_off = (uint32_t)(warp_m * 32 + (lane & 15)) * SROW2 + (lane >> 4) * 16;
    const uint32_t b_off = (uint32_t)(warp_n * 32 + (lane & 7) + ((lane >> 4) & 1) * 8) * SROW2
                         + ((lane >> 3) & 1) * 16;

    for (int t = 0; t < NCHUNK; t++) {
        int s = t & 1;
        if (t + 1 < NCHUNK) {
            int kb = (t + 1) * KC;
            uint32_t stb = sb + ((t + 1) & 1) * STAGEB;
            const __nv_bfloat16* ah = g_behi[p];
            const __nv_bfloat16* al = g_belo[p];
#pragma unroll
            for (int j = 0; j < 4; j++) {
                int lr = ar + 32 * j;
                uint32_t doff = (uint32_t)lr * SROW2 + cs * 16;
                const size_t aoff = (size_t)aidx[j] * MF + kb + cs * 8;
                cpa16(stb + doff, ah + aoff);
                cpa16(stb + TILEB_A + doff, al + aoff);
            }
#pragma unroll
            for (int j = 0; j < 2; j++) {
                int lr = rB + 32 * j;
                uint32_t doff = (uint32_t)lr * SROW2 + cs * 16;
                const size_t boff = (size_t)(col0 + lr) * MF + kb + cs * 8;
                cpa16(stb + 2 * TILEB_A + doff, g_mThi + boff);
                cpa16(stb + 2 * TILEB_A + TILEB_B + doff, g_mTlo + boff);
            }
            CP_COMMIT();
            CP_WAIT(1);
        } else {
            CP_WAIT(0);
        }
        __syncthreads();

        const uint32_t Ah = sb + s * STAGEB;
        const uint32_t Al = Ah + TILEB_A;
        const uint32_t Bh = Ah + 2 * TILEB_A;
        const uint32_t Bl = Bh + TILEB_B;
#pragma unroll
        for (int kk = 0; kk < 4; kk++) {
            const uint32_t kb32 = kk * 32;
            unsigned ah[2][4], al[2][4], bh[2][4], bl[2][4];
#pragma unroll
            for (int fm = 0; fm < 2; fm++) {
                uint32_t ao = a_off + (uint32_t)(fm * 16) * SROW2 + kb32;
                ldm_x4(ah[fm], Ah + ao);
                ldm_x4(al[fm], Al + ao);
            }
#pragma unroll
            for (int pr = 0; pr < 2; pr++) {
                uint32_t bo = b_off + (uint32_t)(pr * 16) * SROW2 + kb32;
                ldm_x4(bh[pr], Bh + bo);
                ldm_x4(bl[pr], Bl + bo);
            }
#pragma unroll
            for (int fm = 0; fm < 2; fm++)
#pragma unroll
                for (int fn = 0; fn < 4; fn++) {
                    const unsigned* ph = &bh[fn >> 1][(fn & 1) * 2];
                    const unsigned* pl = &bl[fn >> 1][(fn & 1) * 2];
                    mma16816(c[fm][fn], ah[fm], ph);
                    mma16816(c[fm][fn], ah[fm], pl);
                    mma16816(c[fm][fn], al[fm], ph);
                }
        }
        __syncthreads();
    }

    // ---- fused ADMM epilogue (all gathered rows unsolved) ----
    float pdx[2][2] = {}, px2[2][2] = {};
#pragma unroll
    for (int fm = 0; fm < 2; fm++) {
#pragma unroll
        for (int rs = 0; rs < 2; rs++) {
            int lrow = warp_m * 32 + fm * 16 + rs * 8 + (lane >> 2);
            int valid = (row0 + lrow < nact);
            int r = valid ? g_idx[row0 + lrow] : 0;
            float ldx = 0.f, lx2 = 0.f;
            if (valid) {
#pragma unroll
                for (int fn = 0; fn < 4; fn++) {
                    int cc = col0 + warp_n * 32 + fn * 8 + (lane & 3) * 2;
                    size_t base = (size_t)r * MF + cc;
                    float2 u2 = *(const float2*)(g_u + base);
                    float2 v2 = *(const float2*)(g_v + base);
                    float2 a2 = *(const float2*)(g_Adb + base);
                    float uu[2] = {u2.x, u2.y}, vv[2] = {v2.x, v2.y}, aa[2] = {a2.x, a2.y};
                    float un[2], vn[2];
#pragma unroll
                    for (int jj = 0; jj < 2; jj++) {
                        float xk = c[fm][fn][rs * 2 + jj];
                        float tt = xk + uu[jj];
                        float av = fabsf(tt) - LAMBDv;
                        float sft = (av > 0.f) ? copysignf(av, tt) : 0.f;
                        un[jj] = tt - sft;
                        vn[jj] = sft;
                        float d = sft - vv[jj];
                        ldx += d * d;
                        lx2 += sft * sft;
                    }
                    *(float2*)(g_u + base) = make_float2(un[0], un[1]);
                    *(float2*)(g_v + base) = make_float2(vn[0], vn[1]);
                    __nv_bfloat16 h0, l0, h1, l1;
                    bsplit(aa[0] + vn[0] - un[0], h0, l0);
                    bsplit(aa[1] + vn[1] - un[1], h1, l1);
                    *(__nv_bfloat162*)(g_behi[pn] + base) = __halves2bfloat162(h0, h1);
                    *(__nv_bfloat162*)(g_belo[pn] + base) = __halves2bfloat162(l0, l1);
                }
            }
            pdx[fm][rs] = ldx;
            px2[fm][rs] = lx2;
        }
    }
#pragma unroll
    for (int fm = 0; fm < 2; fm++) {
#pragma unroll
        for (int rs = 0; rs < 2; rs++) {
            float a = pdx[fm][rs], b = px2[fm][rs];
            a += __shfl_xor_sync(0xffffffffu, a, 1);
            a += __shfl_xor_sync(0xffffffffu, a, 2);
            b += __shfl_xor_sync(0xffffffffu, b, 1);
            b += __shfl_xor_sync(0xffffffffu, b, 2);
            if ((lane & 3) == 0) {
                int rl = warp_m * 32 + fm * 16 + rs * 8 + (lane >> 2);
                red_dx[rl][warp_n] = a;
                red_x2[rl][warp_n] = b;
            }
        }
    }
    __syncthreads();
    if (tid < 128 && row0 + tid < nact) {
        int r = g_idx[row0 + tid];
        g_dx2p[r * 16 + blockIdx.x] = red_dx[tid][0] + red_dx[tid][1];
        g_x2p[r * 16 + blockIdx.x] = red_x2[tid][0] + red_x2[tid][1];
    }
}

// ---------------- convergence flags ----------------
__global__ void converge_kernel() {
    int r = blockIdx.x * 128 + threadIdx.x;
    if (g_solved[r]) return;
    float sdx = 0.f, sx2 = 0.f;
#pragma unroll
    for (int j = 0; j < 16; j++) { sdx += g_dx2p[r * 16 + j]; sx2 += g_x2p[r * 16 + j]; }
    if (sdx < TOL2 * sx2) g_solved[r] = 1;
}

// ---------------- order-preserving compaction of active rows ----------------
__global__ void compact_kernel() {
    __shared__ int scnt[256];
    int t = threadIdx.x;
    int base = t * 4;
    int loc[4];
    int c = 0;
#pragma unroll
    for (int k = 0; k < 4; k++) {
        loc[k] = !g_solved[base + k];
        c += loc[k];
    }
    scnt[t] = c;
    __syncthreads();
    for (int off = 1; off < 256; off <<= 1) {
        int val = (t >= off) ? scnt[t - off] : 0;
        __syncthreads();
        scnt[t] += val;
        __syncthreads();
    }
    int pos = scnt[t] - c;
#pragma unroll
    for (int k = 0; k < 4; k++) {
        if (loc[k]) g_idx[pos++] = base + k;
    }
    if (t == 255) g_nact = scnt[255];
}

// ---------------- enc = solved ? v : 0 ----------------
__global__ void finalize_enc(float* __restrict__ enc) {
    int i = blockIdx.x * blockDim.x + threadIdx.x;  // BATCH*MF/4
    int row = i / (MF / 4);
    float4 vv = ((const float4*)g_v)[i];
    float4 z = make_float4(0.f, 0.f, 0.f, 0.f);
    ((float4*)enc)[i] = g_solved[row] ? vv : z;
}

// ---------------- decoded = encoded @ W ----------------
__global__ void gemm_decode_kernel(const float* __restrict__ W, const float* __restrict__ enc,
                                   float* __restrict__ dec) {
    __shared__ float As[16][64];
    __shared__ float Bs[16][64];
    int tid = threadIdx.x;
    int row0 = blockIdx.y * 64, col0 = blockIdx.x * 64;
    int lr = tid >> 2, kq = tid & 3;
    int kr = tid >> 4, nq = tid & 15;
    int tm = tid >> 4, tn = tid & 15;
    float acc[4][4] = {};
    for (int k0 = 0; k0 < MF; k0 += 16) {
        float4 a4 = *(const float4*)(enc + (size_t)(row0 + lr) * MF + k0 + kq * 4);
        float4 b4 = *(const float4*)(W + (size_t)(k0 + kr) * NF + col0 + nq * 4);
        __syncthreads();
        As[kq * 4 + 0][lr] = a4.x; As[kq * 4 + 1][lr] = a4.y;
        As[kq * 4 + 2][lr] = a4.z; As[kq * 4 + 3][lr] = a4.w;
        *(float4*)&Bs[kr][nq * 4] = b4;
        __syncthreads();
#pragma unroll
        for (int kk = 0; kk < 16; kk++) {
            float4 av = *(const float4*)&As[kk][tm * 4];
            float4 bv = *(const float4*)&Bs[kk][tn * 4];
            float a[4] = {av.x, av.y, av.z, av.w};
            float b[4] = {bv.x, bv.y, bv.z, bv.w};
#pragma unroll
            for (int i = 0; i < 4; i++)
#pragma unroll
                for (int j = 0; j < 4; j++) acc[i][j] += a[i] * b[j];
        }
    }
#pragma unroll
    for (int i = 0; i < 4; i++) {
        float4 o = make_float4(acc[i][0], acc[i][1], acc[i][2], acc[i][3]);
        *(float4*)(dec + (size_t)(row0 + tm * 4 + i) * NF + col0 + tn * 4) = o;
    }
}

// ---------------- launch ----------------
extern "C" void kernel_launch(void* const* d_in, const int* in_sizes, int n_in,
                              void* d_out, int out_size) {
    const float* x = (const float*)d_in[0];      // (1024, 512)
    const float* w = (const float*)d_in[1];      // (1024, 512)
    const float* Minv = (const float*)d_in[2];   // (1024, 1024)
    float* out = (float*)d_out;
    float* enc = out;
    float* dec = out + BATCH * MF;

    static int attr_done = 0;
    if (!attr_done) {
        cudaFuncSetAttribute(admm_iter, cudaFuncAttributeMaxDynamicSharedMemorySize, DYN_SMEM);
        attr_done = 1;
    }

    init_kernel<<<BATCH * MF / 4 / 256, 256>>>();
    prep_minv<<<dim3(32, 32), dim3(32, 8)>>>(Minv);
    gemm_nt_kernel<<<dim3(MF / 64, BATCH / 64), 256>>>(x, w);

    for (int it = 0; it < MAX_ITERS; it++) {
        admm_iter<<<dim3(16, 8), 256, DYN_SMEM>>>(it & 1);
        converge_kernel<<<8, 128>>>();
        compact_kernel<<<1, 256>>>();
    }

    finalize_enc<<<BATCH * MF / 4 / 256, 256>>>(enc);
    gemm_decode_kernel<<<dim3(NF / 64, BATCH / 64), 256>>>(w, enc, dec);
}